// round 3
// baseline (speedup 1.0000x reference)
#include <cuda_runtime.h>
#include <cuda_bf16.h>

// NF4 codebook (float32, matches bitsandbytes / reference exactly)
#define C0  (-1.0f)
#define C1  (-0.6961928009986877f)
#define C2  (-0.5250730514526367f)
#define C3  (-0.39491748809814453f)
#define C4  (-0.28444138169288635f)
#define C5  (-0.18477343022823334f)
#define C6  (-0.09105003625154495f)
#define C7  (0.0f)
#define C8  (0.07958029955625534f)
#define C9  (0.16093020141124725f)
#define C10 (0.24611230194568634f)
#define C11 (0.33791524171829224f)
#define C12 (0.4407098591327667f)
#define C13 (0.5626170039176941f)
#define C14 (0.7229568362236023f)
#define C15 (1.0f)

// Midpoints (decision boundaries), computed in float32 like the reference
#define M0  (0.5f * (C0  + C1 ))
#define M1  (0.5f * (C1  + C2 ))
#define M2  (0.5f * (C2  + C3 ))
#define M3  (0.5f * (C3  + C4 ))
#define M4  (0.5f * (C4  + C5 ))
#define M5  (0.5f * (C5  + C6 ))
#define M6  (0.5f * (C6  + C7 ))
#define M7  (0.5f * (C7  + C8 ))
#define M8  (0.5f * (C8  + C9 ))
#define M9  (0.5f * (C9  + C10))
#define M10 (0.5f * (C10 + C11))
#define M11 (0.5f * (C11 + C12))
#define M12 (0.5f * (C12 + C13))
#define M13 (0.5f * (C13 + C14))
#define M14 (0.5f * (C14 + C15))

static __device__ __forceinline__ float warp_absmax(float v) {
#pragma unroll
    for (int s = 16; s > 0; s >>= 1)
        v = fmaxf(v, __shfl_xor_sync(0xffffffffu, v, s));
    return v;
}

__global__ void __launch_bounds__(256)
nf4_qdq_kernel(const float* __restrict__ x, float* __restrict__ out, int nblk) {
    // one warp per NF4 block of 512 floats (= 128 float4)
    int gw = blockIdx.x * 8 + (threadIdx.x >> 5);
    if (gw >= nblk) return;
    int lane = threadIdx.x & 31;

    const float4* __restrict__ xi = reinterpret_cast<const float4*>(x) + (size_t)gw * 128 + lane;
    float4* __restrict__       xo = reinterpret_cast<float4*>(out)     + (size_t)gw * 128 + lane;

    float4 a = __ldcs(xi + 0);
    float4 b = __ldcs(xi + 32);
    float4 c = __ldcs(xi + 64);
    float4 d = __ldcs(xi + 96);

    // ---- block absmax ----
    float am = fabsf(a.x);
    am = fmaxf(am, fabsf(a.y)); am = fmaxf(am, fabsf(a.z)); am = fmaxf(am, fabsf(a.w));
    am = fmaxf(am, fabsf(b.x)); am = fmaxf(am, fabsf(b.y)); am = fmaxf(am, fabsf(b.z)); am = fmaxf(am, fabsf(b.w));
    am = fmaxf(am, fabsf(c.x)); am = fmaxf(am, fabsf(c.y)); am = fmaxf(am, fabsf(c.z)); am = fmaxf(am, fabsf(c.w));
    am = fmaxf(am, fabsf(d.x)); am = fmaxf(am, fabsf(d.y)); am = fmaxf(am, fabsf(d.z)); am = fmaxf(am, fabsf(d.w));
    am = warp_absmax(am);

    // ---- scaled decision boundaries (15 FMULs per block, amortized) ----
    // compare x > MID[i]*absmax  <=>  x/absmax > MID[i]  (absmax >= 0; absmax==0 => all x==0 => v*am==0, correct)
    float B0  = M0  * am, B1  = M1  * am, B2  = M2  * am, B3  = M3  * am;
    float B4  = M4  * am, B5  = M5  * am, B6  = M6  * am, B7  = M7  * am;
    float B8  = M8  * am, B9  = M9  * am, B10 = M10 * am, B11 = M11 * am;
    float B12 = M12 * am, B13 = M13 * am, B14 = M14 * am;

    auto q = [&](float xv) -> float {
        float v = C0;
        v = (xv > B0)  ? C1  : v;
        v = (xv > B1)  ? C2  : v;
        v = (xv > B2)  ? C3  : v;
        v = (xv > B3)  ? C4  : v;
        v = (xv > B4)  ? C5  : v;
        v = (xv > B5)  ? C6  : v;
        v = (xv > B6)  ? C7  : v;
        v = (xv > B7)  ? C8  : v;
        v = (xv > B8)  ? C9  : v;
        v = (xv > B9)  ? C10 : v;
        v = (xv > B10) ? C11 : v;
        v = (xv > B11) ? C12 : v;
        v = (xv > B12) ? C13 : v;
        v = (xv > B13) ? C14 : v;
        v = (xv > B14) ? C15 : v;
        return v * am;  // exact NF4[idx] * absmax
    };

    a.x = q(a.x); a.y = q(a.y); a.z = q(a.z); a.w = q(a.w);
    b.x = q(b.x); b.y = q(b.y); b.z = q(b.z); b.w = q(b.w);
    c.x = q(c.x); c.y = q(c.y); c.z = q(c.z); c.w = q(c.w);
    d.x = q(d.x); d.y = q(d.y); d.z = q(d.z); d.w = q(d.w);

    __stcs(xo + 0,  a);
    __stcs(xo + 32, b);
    __stcs(xo + 64, c);
    __stcs(xo + 96, d);
}

extern "C" void kernel_launch(void* const* d_in, const int* in_sizes, int n_in,
                              void* d_out, int out_size) {
    const float* x = (const float*)d_in[0];
    float* out = (float*)d_out;
    int n = in_sizes[0];
    int nblk = n / 512;                 // reference requires n % 512 == 0
    int ctas = (nblk + 7) / 8;          // 8 warps (= 8 NF4 blocks) per CTA
    nf4_qdq_kernel<<<ctas, 256>>>(x, out, nblk);
}

// round 4
// speedup vs baseline: 1.3206x; 1.3206x over previous
#include <cuda_runtime.h>
#include <cuda_bf16.h>

// NF4 codebook (float32, matches bitsandbytes / reference exactly)
static __device__ __constant__ float NF4_TBL[16] = {
    -1.0f, -0.6961928009986877f, -0.5250730514526367f, -0.39491748809814453f,
    -0.28444138169288635f, -0.18477343022823334f, -0.09105003625154495f, 0.0f,
    0.07958029955625534f, 0.16093020141124725f, 0.24611230194568634f,
    0.33791524171829224f, 0.4407098591327667f, 0.5626170039176941f,
    0.7229568362236023f, 1.0f
};

// Decision midpoints in t-space: MID_T[j] = ((NF4[j]+NF4[j+1])*0.5f)*32 + 32
// (computed at build time in-kernel from NF4_TBL for float consistency)

#define REPS 8          // lane&7 replication -> conflict-free LDS.128
#define NBUCK 65        // t in [0,64] rounds to 0..64

static __device__ __forceinline__ float warp_absmax(float v) {
#pragma unroll
    for (int s = 16; s > 0; s >>= 1)
        v = fmaxf(v, __shfl_xor_sync(0xffffffffu, v, s));
    return v;
}

__global__ void __launch_bounds__(256)
nf4_qdq_kernel(const float* __restrict__ x, float* __restrict__ out, int nblk) {
    __shared__ float4 lut[NBUCK * REPS];   // {boundary_t, code_lo, code_hi, pad}

    // ---- build the bucket LUT (amortized over 8*512 elements per CTA) ----
    for (int s = threadIdx.x; s < NBUCK * REPS; s += 256) {
        int i = s / REPS;                       // bucket id 0..64
        float loEdge = (float)i - 0.5f;         // bucket covers t in [i-0.5, i+0.5)
        float hiEdge = (float)i + 0.5f;
        int lo = 0, hi = 0;
        float bnd = 3.0e38f;
#pragma unroll
        for (int j = 0; j < 15; j++) {
            float mt = fmaf((NF4_TBL[j] + NF4_TBL[j + 1]) * 0.5f, 32.0f, 32.0f);
            lo += (mt < loEdge);
            hi += (mt < hiEdge);
        }
        if (hi > lo) {  // exactly one midpoint inside this bucket
            bnd = fmaf((NF4_TBL[lo] + NF4_TBL[lo + 1]) * 0.5f, 32.0f, 32.0f);
        }
        float4 e;
        e.x = bnd;
        e.y = NF4_TBL[lo];
        e.z = NF4_TBL[hi];
        e.w = 0.0f;
        lut[s] = e;
    }
    __syncthreads();

    // ---- one warp per NF4 block of 512 floats (= 128 float4) ----
    int gw = blockIdx.x * 8 + (threadIdx.x >> 5);
    if (gw >= nblk) return;
    int lane = threadIdx.x & 31;

    const float4* __restrict__ xi = reinterpret_cast<const float4*>(x) + (size_t)gw * 128 + lane;
    float4* __restrict__       xo = reinterpret_cast<float4*>(out)     + (size_t)gw * 128 + lane;

    float4 a = __ldcs(xi + 0);
    float4 b = __ldcs(xi + 32);
    float4 c = __ldcs(xi + 64);
    float4 d = __ldcs(xi + 96);

    // ---- block absmax (registers + shfl only) ----
    float am = fabsf(a.x);
    am = fmaxf(am, fabsf(a.y)); am = fmaxf(am, fabsf(a.z)); am = fmaxf(am, fabsf(a.w));
    am = fmaxf(am, fabsf(b.x)); am = fmaxf(am, fabsf(b.y)); am = fmaxf(am, fabsf(b.z)); am = fmaxf(am, fabsf(b.w));
    am = fmaxf(am, fabsf(c.x)); am = fmaxf(am, fabsf(c.y)); am = fmaxf(am, fabsf(c.z)); am = fmaxf(am, fabsf(c.w));
    am = fmaxf(am, fabsf(d.x)); am = fmaxf(am, fabsf(d.y)); am = fmaxf(am, fabsf(d.z)); am = fmaxf(am, fabsf(d.w));
    am = warp_absmax(am);

    // per-block scale into t-space (1 divide per 512 elements)
    float s2 = (am > 0.0f) ? (32.0f / am) : 0.0f;

    const float4* __restrict__ lutl = lut + (lane & 7);

    auto q = [&](float xv) -> float {
        float t = fmaf(xv, s2, 32.0f);                 // t in [0, 64]
        float m = t + 8388608.0f;                       // RN -> integer in mantissa
        unsigned bi = (unsigned)(__float_as_int(m) - 0x4B000000);
        bi = min(bi, (unsigned)(NBUCK - 1));            // guard (inf/garbage safe)
        float4 e = lutl[bi * REPS];                     // conflict-free LDS.128
        float v = (t > e.x) ? e.z : e.y;                // resolve the one boundary
        return v * am;                                  // exact NF4[idx] * absmax
    };

    a.x = q(a.x); a.y = q(a.y); a.z = q(a.z); a.w = q(a.w);
    b.x = q(b.x); b.y = q(b.y); b.z = q(b.z); b.w = q(b.w);
    c.x = q(c.x); c.y = q(c.y); c.z = q(c.z); c.w = q(c.w);
    d.x = q(d.x); d.y = q(d.y); d.z = q(d.z); d.w = q(d.w);

    __stcs(xo + 0,  a);
    __stcs(xo + 32, b);
    __stcs(xo + 64, c);
    __stcs(xo + 96, d);
}

extern "C" void kernel_launch(void* const* d_in, const int* in_sizes, int n_in,
                              void* d_out, int out_size) {
    const float* x = (const float*)d_in[0];
    float* out = (float*)d_out;
    int n = in_sizes[0];
    int nblk = n / 512;                 // reference requires n % 512 == 0
    int ctas = (nblk + 7) / 8;          // 8 warps (= 8 NF4 blocks) per CTA
    nf4_qdq_kernel<<<ctas, 256>>>(x, out, nblk);
}